// round 15
// baseline (speedup 1.0000x reference)
#include <cstdint>
#include <cstring>
#include <cuda_runtime.h>
#include <cuda_bf16.h>

#define BATCH 2
#define CH 64
#define HH 224
#define WW 224
#define HW (HH*WW)           // 50176
#define NPIX (BATCH*HW)      // 100352
#define NOFF 18
#define KK 576               // 64*9
#define GEMMBLKS (NPIX/128)  // 784

typedef unsigned long long ull;

// ---------------- scratch (static device memory; no allocations) ----------------
__device__ float g_xh[NPIX*CH];              // NHWC input of stage 1
__device__ float g_off[NPIX*NOFF];           // offsets NHWC
__device__ __nv_bfloat16 g_xgh[(size_t)NPIX*KK];  // gathered samples hi
__device__ __nv_bfloat16 g_xgl[(size_t)NPIX*KK];  // gathered samples lo
__device__ float g_yraw[NPIX*CH];            // pre-BN conv output NHWC
__device__ float g_y1n[NPIX*CH];             // stage-1 normalized output NHWC
__device__ __nv_bfloat16 g_wh1[9*CH*CH];     // conv W hi: [kc][och][c]
__device__ __nv_bfloat16 g_wl1[9*CH*CH];
__device__ __nv_bfloat16 g_wh2[9*CH*CH];
__device__ __nv_bfloat16 g_wl2[9*CH*CH];
__device__ __nv_bfloat16 g_woh1[9*24*CH];    // offset W hi: [tap][och24][c]
__device__ __nv_bfloat16 g_wol1[9*24*CH];
__device__ __nv_bfloat16 g_woh2[9*24*CH];
__device__ __nv_bfloat16 g_wol2[9*24*CH];
__device__ float g_sp[GEMMBLKS*CH];          // partial sums
__device__ float g_qp[GEMMBLKS*CH];          // partial sumsq
__device__ float g_ab[2*CH];                 // per-channel scale a, shift b

__device__ __forceinline__ uint32_t smem_u32(const void* p) {
    uint32_t a;
    asm("{ .reg .u64 t; cvta.to.shared.u64 t, %1; cvt.u32.u64 %0, t; }" : "=r"(a) : "l"(p));
    return a;
}
__device__ __forceinline__ void sts128(uint32_t a, uint4 v) {
    asm volatile("st.shared.v4.b32 [%0], {%1,%2,%3,%4};"
                 :: "r"(a), "r"(v.x), "r"(v.y), "r"(v.z), "r"(v.w) : "memory");
}
__device__ __forceinline__ void sts64(uint32_t a, uint32_t v0, uint32_t v1) {
    asm volatile("st.shared.v2.b32 [%0], {%1,%2};" :: "r"(a), "r"(v0), "r"(v1) : "memory");
}
__device__ __forceinline__ void ldsm4(uint32_t* r, uint32_t addr) {
    asm volatile("ldmatrix.sync.aligned.m8n8.x4.shared.b16 {%0,%1,%2,%3}, [%4];"
                 : "=r"(r[0]), "=r"(r[1]), "=r"(r[2]), "=r"(r[3]) : "r"(addr));
}
__device__ __forceinline__ void ldsm2(uint32_t* r, uint32_t addr) {
    asm volatile("ldmatrix.sync.aligned.m8n8.x2.shared.b16 {%0,%1}, [%2];"
                 : "=r"(r[0]), "=r"(r[1]) : "r"(addr));
}
__device__ __forceinline__ void mma16816(float* d, const uint32_t* a, uint32_t b0, uint32_t b1) {
    asm volatile(
        "mma.sync.aligned.m16n8k16.row.col.f32.bf16.bf16.f32 "
        "{%0,%1,%2,%3}, {%4,%5,%6,%7}, {%8,%9}, {%0,%1,%2,%3};"
        : "+f"(d[0]), "+f"(d[1]), "+f"(d[2]), "+f"(d[3])
        : "r"(a[0]), "r"(a[1]), "r"(a[2]), "r"(a[3]), "r"(b0), "r"(b1));
}

// ---------------- NCHW -> NHWC transpose ----------------
__global__ __launch_bounds__(256) void k_nchw2nhwc(const float* __restrict__ x) {
    __shared__ float tile[32][33];
    int b = blockIdx.z;
    int s0 = blockIdx.x * 32, c0 = blockIdx.y * 32;
    int tx = threadIdx.x, ty = threadIdx.y;
#pragma unroll
    for (int j = 0; j < 4; j++) {
        int c = c0 + ty + j*8;
        tile[ty + j*8][tx] = x[(b*CH + c)*HW + s0 + tx];
    }
    __syncthreads();
#pragma unroll
    for (int j = 0; j < 4; j++) {
        int s = s0 + ty + j*8;
        g_xh[(b*HW + s)*CH + c0 + tx] = tile[tx][ty + j*8];
    }
}

// ---------------- combined W prep: conv (blocks 0-143) + offset (blocks 144-197) ----
__global__ void k_prepall(const float* __restrict__ wconv, const float* __restrict__ woff,
                          __nv_bfloat16* __restrict__ wh,  __nv_bfloat16* __restrict__ wl,
                          __nv_bfloat16* __restrict__ woh, __nv_bfloat16* __restrict__ wol) {
    int blk = blockIdx.x;
    if (blk < 144) {
        int j = blk*256 + threadIdx.x;
        int cl = j & 63, och = (j >> 6) & 63, kc = j >> 12;
        float wv = wconv[och*KK + cl*9 + kc];
        __nv_bfloat16 h = __float2bfloat16(wv);
        wh[j] = h;
        wl[j] = __float2bfloat16(wv - __bfloat162float(h));
    } else {
        int j = (blk - 144)*256 + threadIdx.x;   // 54 blocks x 256 = 13824 = 9*24*64
        int c = j & 63;
        int tap = j / 1536;
        int och = (j - tap*1536) >> 6;           // 0..23
        float wv = 0.f;
        if (och < NOFF) wv = woff[och*KK + c*9 + tap];
        __nv_bfloat16 h = __float2bfloat16(wv);
        woh[j] = h;
        wol[j] = __float2bfloat16(wv - __bfloat162float(h));
    }
}

// ---------------- offset conv as tensor GEMM: 64px x 2 rows x 18och ----------
// 256 threads (8 warps: warp = (row ry, px16 wp)). Patch rows h0-1..h0+2 shared
// between the two output rows -> load work per output halved vs 1-row tile.
// smem: patch hi/lo [plane(4)][w(66)][c(64)] bf16 + B hi/lo [tap(9)][och(24)][c(64)]
#define OG_PH   0
#define OG_PL   33792
#define OG_BH   67584
#define OG_BL   95232
#define OG_SMEM 122880

__global__ __launch_bounds__(256, 1)
void k_offgemm(const float* __restrict__ in,
               const __nv_bfloat16* __restrict__ wh,
               const __nv_bfloat16* __restrict__ wl,
               const float* __restrict__ boff) {
    extern __shared__ char smem[];
    uint32_t sb = smem_u32(smem);
    int t = threadIdx.x;
    int w = t >> 5, lane = t & 31;
    int w0 = blockIdx.x * 64, h0 = blockIdx.y * 2, b = blockIdx.z;

    // load B (hi/lo): 216 rows x 128B, per-row XOR swizzle (key = row&7; 24%8==0)
    {
        const uint4* g4h = (const uint4*)wh;
        const uint4* g4l = (const uint4*)wl;
        for (int j = t; j < 1728; j += 256) {
            int row = j >> 3, q = j & 7;
            uint32_t o = (uint32_t)row*128 + (uint32_t)((q ^ (row & 7)) << 4);
            sts128(sb + OG_BH + o, g4h[j]);
            sts128(sb + OG_BL + o, g4l[j]);
        }
    }
    // patch: input rows h0-1..h0+2 (4 planes), cols w0-1..w0+64, zero-padded
    for (int j = t; j < 4224; j += 256) {       // 4*66 rows x 16 float4
        int row = j >> 4, e = j & 15;
        int plane = row / 66, p = row - plane*66;
        int hr = h0 - 1 + plane, wc = w0 - 1 + p;
        float4 v = make_float4(0.f, 0.f, 0.f, 0.f);
        if ((unsigned)hr < (unsigned)HH && (unsigned)wc < (unsigned)WW)
            v = *(const float4*)(in + ((size_t)((b*HH + hr)*WW + wc))*CH + e*4);
        __nv_bfloat162 h01 = __floats2bfloat162_rn(v.x, v.y);
        __nv_bfloat162 h23 = __floats2bfloat162_rn(v.z, v.w);
        float2 f01 = __bfloat1622float2(h01);
        float2 f23 = __bfloat1622float2(h23);
        __nv_bfloat162 l01 = __floats2bfloat162_rn(v.x - f01.x, v.y - f01.y);
        __nv_bfloat162 l23 = __floats2bfloat162_rn(v.z - f23.x, v.w - f23.y);
        unsigned int uh01, uh23, ul01, ul23;
        memcpy(&uh01, &h01, 4); memcpy(&uh23, &h23, 4);
        memcpy(&ul01, &l01, 4); memcpy(&ul23, &l23, 4);
        // key = within-plane pixel index (p & 7), matching ldsm side
        uint32_t addr = (uint32_t)row*128 + (uint32_t)((((e >> 1) ^ (p & 7)) << 4) + (e & 1)*8);
        sts64(sb + OG_PH + addr, uh01, uh23);
        sts64(sb + OG_PL + addr, ul01, ul23);
    }
    __syncthreads();

    int ry = w >> 2, wp = w & 3;         // output row (0/1), px-group (0..3)
    int m = lane >> 3, r = lane & 7;
    int apx = 16*wp + (m & 1)*8 + r;     // pixel 0..63 within output row
    int ac0 = m >> 1;
    int bochp = (m >> 1)*8 + r, bc0 = m & 1;
    int l16 = lane & 15, r2 = l16 & 7, cH = l16 >> 3;   // x2 address lanes

    float acc[3][4];
#pragma unroll
    for (int n = 0; n < 3; n++)
#pragma unroll
        for (int j = 0; j < 4; j++) acc[n][j] = 0.f;

#pragma unroll
    for (int tap = 0; tap < 9; tap++) {
        int kx = tap / 3, ky = tap - kx*3;
        int plane = ry + kx;                 // 0..3
        int arow = apx + ky;                 // within-plane pixel row
        uint32_t aoff = (uint32_t)(plane*8448 + arow*128);
        int akey = arow & 7;
        uint32_t bRow01 = (uint32_t)(tap*24 + bochp)*128;        // och 0-15 via x4
        uint32_t bRow2  = (uint32_t)(tap*24 + 16 + r2)*128;      // och 16-23 via x2
#pragma unroll
        for (int kk = 0; kk < 4; kk++) {
            uint32_t ax  = aoff + (uint32_t)(((kk*2 + ac0) ^ akey) << 4);
            uint32_t bx  = (uint32_t)(((kk*2 + bc0) ^ r) << 4);
            uint32_t bx2 = (uint32_t)(((kk*2 + cH) ^ r2) << 4);
            uint32_t ah[4], al[4], b01h[4], b01l[4], b2h[2], b2l[2];
            ldsm4(ah, sb + OG_PH + ax);
            ldsm4(al, sb + OG_PL + ax);
            ldsm4(b01h, sb + OG_BH + bRow01 + bx);
            ldsm4(b01l, sb + OG_BL + bRow01 + bx);
            ldsm2(b2h, sb + OG_BH + bRow2 + bx2);
            ldsm2(b2l, sb + OG_BL + bRow2 + bx2);
            mma16816(acc[0], ah, b01h[0], b01h[1]);
            mma16816(acc[1], ah, b01h[2], b01h[3]);
            mma16816(acc[2], ah, b2h[0],  b2h[1]);
            mma16816(acc[0], ah, b01l[0], b01l[1]);
            mma16816(acc[1], ah, b01l[2], b01l[3]);
            mma16816(acc[2], ah, b2l[0],  b2l[1]);
            mma16816(acc[0], al, b01h[0], b01h[1]);
            mma16816(acc[1], al, b01h[2], b01h[3]);
            mma16816(acc[2], al, b2h[0],  b2h[1]);
        }
    }

    // epilogue: bias + stage 128x24 fp32 (2 rows x 64 px), write g_off
    __syncthreads();
    float* stg = (float*)smem;
    int g = lane >> 2, tid4 = lane & 3;
#pragma unroll
    for (int nt = 0; nt < 3; nt++) {
        int col = nt*8 + tid4*2;
        float b0v = (col     < NOFF) ? boff[col]     : 0.f;
        float b1v = (col + 1 < NOFF) ? boff[col + 1] : 0.f;
        int row0 = ry*64 + 16*wp + g;
        stg[row0*24 + col]       = acc[nt][0] + b0v;
        stg[row0*24 + col + 1]   = acc[nt][1] + b1v;
        stg[(row0+8)*24 + col]   = acc[nt][2] + b0v;
        stg[(row0+8)*24 + col+1] = acc[nt][3] + b1v;
    }
    __syncthreads();
    int px = t >> 1, half = t & 1;          // px 0..127
    int ry2 = px >> 6, pxl = px & 63;
    int wpos = w0 + pxl, hrow = h0 + ry2;
    if (wpos < WW) {
        int base = ((b*HH + hrow)*WW + wpos)*NOFF + half*9;
#pragma unroll
        for (int i = 0; i < 9; i++)
            g_off[base + i] = stg[px*24 + half*9 + i];
    }
}

// ---------------- gather: bilinear sample -> bf16 hi/lo ----------------
__global__ __launch_bounds__(256) void k_gather(const float* __restrict__ in,
                                                __nv_bfloat16* __restrict__ xgh,
                                                __nv_bfloat16* __restrict__ xgl) {
    __shared__ int4   gA[288];
    __shared__ float4 gW[288];
    __shared__ int    gO[288];
    int t = threadIdx.x;
    int pix0 = blockIdx.x * 32;
    int b = pix0 / HW; int hw = pix0 - b*HW;
    int h = hw / WW;  int w0 = hw - h*WW;

    for (int j = t; j < 288; j += 256) {
        int p = j / 9; int i = j - p*9;
        int pix = pix0 + p;
        float ox = g_off[pix*NOFF + i];
        float oy = g_off[pix*NOFF + 9 + i];
        float px = (float)(h + (i/3)) + ox;
        float py = (float)(w0 + p + (i%3)) + oy;
        float fx = floorf(px), fy = floorf(py);
        int x0 = (int)fx, y0 = (int)fy;
        int x1 = x0 + 1, y1 = y0 + 1;
        x0 = min(max(x0, 0), HH-1); x1 = min(max(x1, 0), HH-1);
        y0 = min(max(y0, 0), WW-1); y1 = min(max(y1, 0), WW-1);
        float pxc = fminf(fmaxf(px, 0.f), (float)(HH-1));
        float pyc = fminf(fmaxf(py, 0.f), (float)(WW-1));
        float wx0 = 1.f + (float)x0 - pxc;
        float wx1 = 1.f - (float)x1 + pxc;
        float wy0 = 1.f + (float)y0 - pyc;
        float wy1 = 1.f - (float)y1 + pyc;
        int base = b * HW;
        gA[j] = make_int4((base + x0*WW + y0)*CH, (base + x1*WW + y1)*CH,
                          (base + x0*WW + y1)*CH, (base + x1*WW + y0)*CH);
        gW[j] = make_float4(wx0*wy0, wx1*wy1, wx0*wy1, wx1*wy0);
        gO[j] = pix*KK + i*64;
    }
    __syncthreads();

    int c4 = (t & 15) * 4;
    int d0 = t >> 4;
#pragma unroll 3
    for (int it = 0; it < 18; it++) {
        int desc = d0 + it*16;
        int4 a = gA[desc]; float4 g = gW[desc];
        float4 v0 = *(const float4*)(in + a.x + c4);
        float4 v1 = *(const float4*)(in + a.y + c4);
        float4 v2 = *(const float4*)(in + a.z + c4);
        float4 v3 = *(const float4*)(in + a.w + c4);
        float4 r;
        r.x = fmaf(g.w, v3.x, fmaf(g.z, v2.x, fmaf(g.y, v1.x, g.x*v0.x)));
        r.y = fmaf(g.w, v3.y, fmaf(g.z, v2.y, fmaf(g.y, v1.y, g.x*v0.y)));
        r.z = fmaf(g.w, v3.z, fmaf(g.z, v2.z, fmaf(g.y, v1.z, g.x*v0.z)));
        r.w = fmaf(g.w, v3.w, fmaf(g.z, v2.w, fmaf(g.y, v1.w, g.x*v0.w)));
        __nv_bfloat162 h01 = __floats2bfloat162_rn(r.x, r.y);
        __nv_bfloat162 h23 = __floats2bfloat162_rn(r.z, r.w);
        float2 f01 = __bfloat1622float2(h01);
        float2 f23 = __bfloat1622float2(h23);
        __nv_bfloat162 l01 = __floats2bfloat162_rn(r.x - f01.x, r.y - f01.y);
        __nv_bfloat162 l23 = __floats2bfloat162_rn(r.z - f23.x, r.w - f23.y);
        unsigned int uh01, uh23, ul01, ul23;
        memcpy(&uh01, &h01, 4); memcpy(&uh23, &h23, 4);
        memcpy(&ul01, &l01, 4); memcpy(&ul23, &l23, 4);
        size_t off = (size_t)gO[desc] + c4;
        *(uint2*)(xgh + off) = make_uint2(uh01, uh23);
        *(uint2*)(xgl + off) = make_uint2(ul01, ul23);
    }
}

// ---------------- mma.sync bf16 GEMM: 128px x 64och, K=576, hi/lo split ----------------
#define SM_AH   0
#define SM_AL   16384
#define SM_BH   32768
#define SM_BL   40960
#define SM_TOTAL 49152

__global__ __launch_bounds__(256, 2)
void k_gemmtc(const __nv_bfloat16* __restrict__ xh,
              const __nv_bfloat16* __restrict__ xl,
              const __nv_bfloat16* __restrict__ wh,
              const __nv_bfloat16* __restrict__ wl,
              float* __restrict__ yout) {
    extern __shared__ char smem[];
    uint32_t sb = smem_u32(smem);
    int t = threadIdx.x;
    int w = t >> 5, lane = t & 31;
    int pix0 = blockIdx.x * 128;

    int apx = t >> 1, ahalf = t & 1;
    int boch = t >> 2, bq = t & 3;
    const uint4* gah = (const uint4*)(xh + (size_t)(pix0 + apx)*KK) + ahalf*4;
    const uint4* gal = (const uint4*)(xl + (size_t)(pix0 + apx)*KK) + ahalf*4;
    const uint4* gbh = (const uint4*)wh + boch*8 + bq*2;
    const uint4* gbl = (const uint4*)wl + boch*8 + bq*2;
    int asw = apx & 7, bsw = boch & 7;

    int pg = w >> 1, og = w & 1;
    int m = lane >> 3, r = lane & 7;
    uint32_t aOff0 = (uint32_t)(32*pg + (m & 1)*8 + r) * 128;
    uint32_t aOff1 = aOff0 + 16*128;
    int ac0 = m >> 1;
    int bochp = (m >> 1)*8 + r;
    int bc0 = m & 1;
    int obase = 32*og;

    float acc[2][4][4];
#pragma unroll
    for (int rt = 0; rt < 2; rt++)
#pragma unroll
        for (int n = 0; n < 4; n++)
#pragma unroll
            for (int j = 0; j < 4; j++) acc[rt][n][j] = 0.f;

    uint4 ra[4], rl[4], rbh[2], rbl[2];
#define LOADCH(kc) do { \
        ra[0]=gah[(kc)*8+0]; ra[1]=gah[(kc)*8+1]; ra[2]=gah[(kc)*8+2]; ra[3]=gah[(kc)*8+3]; \
        rl[0]=gal[(kc)*8+0]; rl[1]=gal[(kc)*8+1]; rl[2]=gal[(kc)*8+2]; rl[3]=gal[(kc)*8+3]; \
        rbh[0]=gbh[(kc)*512+0]; rbh[1]=gbh[(kc)*512+1]; \
        rbl[0]=gbl[(kc)*512+0]; rbl[1]=gbl[(kc)*512+1]; \
    } while (0)

    LOADCH(0);
    for (int kc = 0; kc < 9; kc++) {
        __syncthreads();
#pragma unroll
        for (int q = 0; q < 4; q++) {
            uint32_t o = (uint32_t)apx*128 + (uint32_t)(((ahalf*4 + q) ^ asw) << 4);
            sts128(sb + SM_AH + o, ra[q]);
            sts128(sb + SM_AL + o, rl[q]);
        }
#pragma unroll
        for (int q = 0; q < 2; q++) {
            uint32_t o = (uint32_t)boch*128 + (uint32_t)(((bq*2 + q) ^ bsw) << 4);
            sts128(sb + SM_BH + o, rbh[q]);
            sts128(sb + SM_BL + o, rbl[q]);
        }
        __syncthreads();
        if (kc < 8) LOADCH(kc + 1);

#pragma unroll
        for (int kk = 0; kk < 4; kk++) {
            uint32_t ah0[4], al0[4], ah1[4], al1[4];
            uint32_t kx = (uint32_t)(((kk*2 + ac0) ^ r) << 4);
            ldsm4(ah0, sb + SM_AH + aOff0 + kx);
            ldsm4(al0, sb + SM_AL + aOff0 + kx);
            ldsm4(ah1, sb + SM_AH + aOff1 + kx);
            ldsm4(al1, sb + SM_AL + aOff1 + kx);
            uint32_t bco = (uint32_t)(((kk*2 + bc0) ^ r) << 4);
#pragma unroll
            for (int nt = 0; nt < 2; nt++) {
                uint32_t bh[4], bl[4];
                uint32_t bo = (uint32_t)(obase + 16*nt + bochp)*128 + bco;
                ldsm4(bh, sb + SM_BH + bo);
                ldsm4(bl, sb + SM_BL + bo);
                mma16816(acc[0][2*nt],   ah0, bh[0], bh[1]);
                mma16816(acc[0][2*nt+1], ah0, bh[2], bh[3]);
                mma16816(acc[0][2*nt],   ah0, bl[0], bl[1]);
                mma16816(acc[0][2*nt+1], ah0, bl[2], bl[3]);
                mma16816(acc[0][2*nt],   al0, bh[0], bh[1]);
                mma16816(acc[0][2*nt+1], al0, bh[2], bh[3]);
                mma16816(acc[1][2*nt],   ah1, bh[0], bh[1]);
                mma16816(acc[1][2*nt+1], ah1, bh[2], bh[3]);
                mma16816(acc[1][2*nt],   ah1, bl[0], bl[1]);
                mma16816(acc[1][2*nt+1], ah1, bl[2], bl[3]);
                mma16816(acc[1][2*nt],   al1, bh[0], bh[1]);
                mma16816(acc[1][2*nt+1], al1, bh[2], bh[3]);
            }
        }
    }
#undef LOADCH

    __syncthreads();
    float* stg = (float*)smem;
    int g = lane >> 2, tid4 = lane & 3;
#pragma unroll
    for (int rt = 0; rt < 2; rt++) {
#pragma unroll
        for (int n = 0; n < 4; n++) {
            int row0 = 32*pg + 16*rt + g;
            int col = obase + n*8 + tid4*2;
            *(float2*)(stg + row0*64 + col)     = make_float2(acc[rt][n][0], acc[rt][n][1]);
            *(float2*)(stg + (row0+8)*64 + col) = make_float2(acc[rt][n][2], acc[rt][n][3]);
        }
    }
    __syncthreads();

    int och = t & 63, grp = t >> 6;
    float s = 0.f, q = 0.f;
#pragma unroll 4
    for (int j = 0; j < 32; j++) {
        float v = stg[(grp*32 + j)*64 + och];
        s += v;
        q = fmaf(v, v, q);
    }
    float* rs = (float*)(smem + SM_BH);
    float* rq = rs + 256;
    rs[t] = s; rq[t] = q;

    float4* stg4 = (float4*)stg;
    float4* y4 = (float4*)(yout + (size_t)pix0*CH);
#pragma unroll
    for (int j = 0; j < 8; j++) y4[j*256 + t] = stg4[j*256 + t];

    __syncthreads();
    if (t < 64) {
        s = rs[t] + rs[t+64] + rs[t+128] + rs[t+192];
        q = rq[t] + rq[t+64] + rq[t+128] + rq[t+192];
        g_sp[blockIdx.x*64 + t] = s;
        g_qp[blockIdx.x*64 + t] = q;
    }
}

// ---------------- BN finish: reduce 784 partials ----------------
__global__ __launch_bounds__(256) void k_bnfinish(const float* __restrict__ gamma,
                                                  const float* __restrict__ beta) {
    __shared__ float ss[256], sq[256];
    int t = threadIdx.x;
    int c = t & 63, sub = t >> 6;
    float s = 0.f, q = 0.f;
    for (int i = sub; i < GEMMBLKS; i += 4) {
        s += g_sp[i*64 + c];
        q += g_qp[i*64 + c];
    }
    ss[t] = s; sq[t] = q;
    __syncthreads();
    if (t < 64) {
        s = ss[t] + ss[t+64] + ss[t+128] + ss[t+192];
        q = sq[t] + sq[t+64] + sq[t+128] + sq[t+192];
        float inv = 1.f / (float)NPIX;
        float mean = s * inv;
        float var = fmaxf(q * inv - mean*mean, 0.f);
        float r = rsqrtf(var + 1e-5f);
        float a = gamma[t] * r;
        g_ab[t] = a;
        g_ab[64 + t] = beta[t] - mean * a;
    }
}

// ---------------- BN apply + relu, NHWC -> NHWC (stage-1 output) ----------------
__global__ __launch_bounds__(256) void k_bnapply_nhwc(const float* __restrict__ y) {
    int v = blockIdx.x * 256 + threadIdx.x;
    float4 t4 = ((const float4*)y)[v];
    int c = (v & 15) * 4;
    float4 r;
    r.x = fmaxf(fmaf(t4.x, g_ab[c+0], g_ab[64+c+0]), 0.f);
    r.y = fmaxf(fmaf(t4.y, g_ab[c+1], g_ab[64+c+1]), 0.f);
    r.z = fmaxf(fmaf(t4.z, g_ab[c+2], g_ab[64+c+2]), 0.f);
    r.w = fmaxf(fmaf(t4.w, g_ab[c+3], g_ab[64+c+3]), 0.f);
    ((float4*)g_y1n)[v] = r;
}

// ---------------- BN apply + relu + NHWC -> NCHW (final output) ----------------
__global__ __launch_bounds__(256) void k_bnapply_nchw(const float* __restrict__ y,
                                                      float* __restrict__ out) {
    __shared__ float tile[64*33];
    int t = threadIdx.x;
    int pix0 = blockIdx.x * 32;
    int b = pix0 / HW, hw0 = pix0 - b*HW;
    int c = t & 63, q = t >> 6;
    float a = g_ab[c], bb = g_ab[64 + c];
#pragma unroll
    for (int j = 0; j < 8; j++) {
        int p = q*8 + j;
        float v = y[(pix0 + p)*CH + c];
        tile[c*33 + p] = fmaxf(fmaf(v, a, bb), 0.f);
    }
    __syncthreads();
    int p2 = t & 31, cq = t >> 5;
#pragma unroll
    for (int j = 0; j < 8; j++) {
        int cc = cq*8 + j;
        out[(b*CH + cc)*HW + hw0 + p2] = tile[cc*33 + p2];
    }
}

// ---------------- launch ----------------
extern "C" void kernel_launch(void* const* d_in, const int* in_sizes, int n_in,
                              void* d_out, int out_size) {
    const float* x      = (const float*)d_in[0];
    const float* woff1  = (const float*)d_in[1];
    const float* boff1  = (const float*)d_in[2];
    const float* wconv1 = (const float*)d_in[3];
    const float* gamma1 = (const float*)d_in[4];
    const float* beta1  = (const float*)d_in[5];
    const float* woff2  = (const float*)d_in[6];
    const float* boff2  = (const float*)d_in[7];
    const float* wconv2 = (const float*)d_in[8];
    const float* gamma2 = (const float*)d_in[9];
    const float* beta2  = (const float*)d_in[10];
    float* out = (float*)d_out;

    float *p_xh, *p_y1n, *p_yraw;
    __nv_bfloat16 *p_xgh, *p_xgl, *p_wh1, *p_wl1, *p_wh2, *p_wl2;
    __nv_bfloat16 *p_woh1, *p_wol1, *p_woh2, *p_wol2;
    cudaGetSymbolAddress((void**)&p_xh,   g_xh);
    cudaGetSymbolAddress((void**)&p_y1n,  g_y1n);
    cudaGetSymbolAddress((void**)&p_yraw, g_yraw);
    cudaGetSymbolAddress((void**)&p_xgh,  g_xgh);
    cudaGetSymbolAddress((void**)&p_xgl,  g_xgl);
    cudaGetSymbolAddress((void**)&p_wh1,  g_wh1);
    cudaGetSymbolAddress((void**)&p_wl1,  g_wl1);
    cudaGetSymbolAddress((void**)&p_wh2,  g_wh2);
    cudaGetSymbolAddress((void**)&p_wl2,  g_wl2);
    cudaGetSymbolAddress((void**)&p_woh1, g_woh1);
    cudaGetSymbolAddress((void**)&p_wol1, g_wol1);
    cudaGetSymbolAddress((void**)&p_woh2, g_woh2);
    cudaGetSymbolAddress((void**)&p_wol2, g_wol2);

    cudaFuncSetAttribute(k_offgemm, cudaFuncAttributeMaxDynamicSharedMemorySize, OG_SMEM);
    cudaFuncSetAttribute(k_gemmtc,  cudaFuncAttributeMaxDynamicSharedMemorySize, SM_TOTAL);

    // stage 1  (k_offgemm is launch 4 -> ncu capture slot)
    k_nchw2nhwc<<<dim3(HW/32, 2, BATCH), dim3(32, 8)>>>(x);                           // 1
    k_prepall<<<198, 256>>>(wconv1, woff1, p_wh1, p_wl1, p_woh1, p_wol1);             // 2
    k_prepall<<<198, 256>>>(wconv2, woff2, p_wh2, p_wl2, p_woh2, p_wol2);             // 3
    k_offgemm<<<dim3(4, HH/2, BATCH), 256, OG_SMEM>>>(p_xh, p_woh1, p_wol1, boff1);   // 4
    k_gather<<<NPIX/32, 256>>>(p_xh, p_xgh, p_xgl);                                   // 5
    k_gemmtc<<<GEMMBLKS, 256, SM_TOTAL>>>(p_xgh, p_xgl, p_wh1, p_wl1, p_yraw);        // 6
    k_bnfinish<<<1, 256>>>(gamma1, beta1);                                            // 7
    k_bnapply_nhwc<<<NPIX*CH/4/256, 256>>>(p_yraw);                                   // 8

    // stage 2
    k_offgemm<<<dim3(4, HH/2, BATCH), 256, OG_SMEM>>>(p_y1n, p_woh2, p_wol2, boff2);  // 9
    k_gather<<<NPIX/32, 256>>>(p_y1n, p_xgh, p_xgl);                                  // 10
    k_gemmtc<<<GEMMBLKS, 256, SM_TOTAL>>>(p_xgh, p_xgl, p_wh2, p_wl2, p_yraw);        // 11
    k_bnfinish<<<1, 256>>>(gamma2, beta2);                                            // 12
    k_bnapply_nchw<<<NPIX/32, 256>>>(p_yraw, out);                                    // 13
}

// round 16
// speedup vs baseline: 1.0360x; 1.0360x over previous
#include <cstdint>
#include <cstring>
#include <cuda_runtime.h>
#include <cuda_bf16.h>

#define BATCH 2
#define CH 64
#define HH 224
#define WW 224
#define HW (HH*WW)           // 50176
#define NPIX (BATCH*HW)      // 100352
#define NOFF 18
#define KK 576               // 64*9
#define GEMMBLKS (NPIX/128)  // 784

typedef unsigned long long ull;

// ---------------- scratch (static device memory; no allocations) ----------------
__device__ float g_xh[NPIX*CH];              // NHWC input of stage 1
__device__ float g_off[NPIX*NOFF];           // offsets NHWC
__device__ __nv_bfloat16 g_xgh[(size_t)NPIX*KK];  // gathered samples hi
__device__ __nv_bfloat16 g_xgl[(size_t)NPIX*KK];  // gathered samples lo
__device__ float g_yraw[NPIX*CH];            // pre-BN conv output NHWC
__device__ float g_y1n[NPIX*CH];             // stage-1 normalized output NHWC
__device__ __nv_bfloat16 g_wh1[9*CH*CH];     // conv W hi: [kc][och][c]
__device__ __nv_bfloat16 g_wl1[9*CH*CH];
__device__ __nv_bfloat16 g_wh2[9*CH*CH];
__device__ __nv_bfloat16 g_wl2[9*CH*CH];
__device__ __nv_bfloat16 g_woh1[9*24*CH];    // offset W hi: [tap][och24][c]
__device__ __nv_bfloat16 g_wol1[9*24*CH];
__device__ __nv_bfloat16 g_woh2[9*24*CH];
__device__ __nv_bfloat16 g_wol2[9*24*CH];
__device__ float g_sp[GEMMBLKS*CH];          // partial sums
__device__ float g_qp[GEMMBLKS*CH];          // partial sumsq
__device__ float g_ab[2*CH];                 // per-channel scale a, shift b

__device__ __forceinline__ uint32_t smem_u32(const void* p) {
    uint32_t a;
    asm("{ .reg .u64 t; cvta.to.shared.u64 t, %1; cvt.u32.u64 %0, t; }" : "=r"(a) : "l"(p));
    return a;
}
__device__ __forceinline__ void sts128(uint32_t a, uint4 v) {
    asm volatile("st.shared.v4.b32 [%0], {%1,%2,%3,%4};"
                 :: "r"(a), "r"(v.x), "r"(v.y), "r"(v.z), "r"(v.w) : "memory");
}
__device__ __forceinline__ void sts64(uint32_t a, uint32_t v0, uint32_t v1) {
    asm volatile("st.shared.v2.b32 [%0], {%1,%2};" :: "r"(a), "r"(v0), "r"(v1) : "memory");
}
__device__ __forceinline__ void ldsm4(uint32_t* r, uint32_t addr) {
    asm volatile("ldmatrix.sync.aligned.m8n8.x4.shared.b16 {%0,%1,%2,%3}, [%4];"
                 : "=r"(r[0]), "=r"(r[1]), "=r"(r[2]), "=r"(r[3]) : "r"(addr));
}
__device__ __forceinline__ void ldsm2(uint32_t* r, uint32_t addr) {
    asm volatile("ldmatrix.sync.aligned.m8n8.x2.shared.b16 {%0,%1}, [%2];"
                 : "=r"(r[0]), "=r"(r[1]) : "r"(addr));
}
__device__ __forceinline__ void mma16816(float* d, const uint32_t* a, uint32_t b0, uint32_t b1) {
    asm volatile(
        "mma.sync.aligned.m16n8k16.row.col.f32.bf16.bf16.f32 "
        "{%0,%1,%2,%3}, {%4,%5,%6,%7}, {%8,%9}, {%0,%1,%2,%3};"
        : "+f"(d[0]), "+f"(d[1]), "+f"(d[2]), "+f"(d[3])
        : "r"(a[0]), "r"(a[1]), "r"(a[2]), "r"(a[3]), "r"(b0), "r"(b1));
}

// ---------------- NCHW -> NHWC transpose ----------------
__global__ __launch_bounds__(256) void k_nchw2nhwc(const float* __restrict__ x) {
    __shared__ float tile[32][33];
    int b = blockIdx.z;
    int s0 = blockIdx.x * 32, c0 = blockIdx.y * 32;
    int tx = threadIdx.x, ty = threadIdx.y;
#pragma unroll
    for (int j = 0; j < 4; j++) {
        int c = c0 + ty + j*8;
        tile[ty + j*8][tx] = x[(b*CH + c)*HW + s0 + tx];
    }
    __syncthreads();
#pragma unroll
    for (int j = 0; j < 4; j++) {
        int s = s0 + ty + j*8;
        g_xh[(b*HW + s)*CH + c0 + tx] = tile[tx][ty + j*8];
    }
}

// ---------------- combined W prep: conv (blocks 0-143) + offset (blocks 144-197) ----
__global__ void k_prepall(const float* __restrict__ wconv, const float* __restrict__ woff,
                          __nv_bfloat16* __restrict__ wh,  __nv_bfloat16* __restrict__ wl,
                          __nv_bfloat16* __restrict__ woh, __nv_bfloat16* __restrict__ wol) {
    int blk = blockIdx.x;
    if (blk < 144) {
        int j = blk*256 + threadIdx.x;
        int cl = j & 63, och = (j >> 6) & 63, kc = j >> 12;
        float wv = wconv[och*KK + cl*9 + kc];
        __nv_bfloat16 h = __float2bfloat16(wv);
        wh[j] = h;
        wl[j] = __float2bfloat16(wv - __bfloat162float(h));
    } else {
        int j = (blk - 144)*256 + threadIdx.x;   // 54 blocks x 256 = 13824 = 9*24*64
        int c = j & 63;
        int tap = j / 1536;
        int och = (j - tap*1536) >> 6;           // 0..23
        float wv = 0.f;
        if (och < NOFF) wv = woff[och*KK + c*9 + tap];
        __nv_bfloat16 h = __float2bfloat16(wv);
        woh[j] = h;
        wol[j] = __float2bfloat16(wv - __bfloat162float(h));
    }
}

// ---------------- offset conv as tensor GEMM: 64px x 18och, 4-row loop ----------
// 128 threads (4 warps, each 16px), 2 CTAs/SM. Per block: B loaded ONCE,
// 3-plane circular patch buffer (slot = (hr+3)%3) -> 1 new plane per row.
// smem: patch hi/lo 3*8448 ea + B hi/lo 27648 ea + stg 6144
#define OG_PH   0
#define OG_PL   25344
#define OG_BH   50688
#define OG_BL   78336
#define OG_STG  105984
#define OG_SMEM 112128
#define OG_ROWS 4

__device__ __forceinline__ void og_loadplane(uint32_t sb, const float* __restrict__ in,
                                             int b, int w0, int hr, int t) {
    uint32_t pbase = (uint32_t)((hr + 3) % 3) * 8448u;
    for (int j = t; j < 1056; j += 128) {      // 66 rows x 16 float4
        int p = j >> 4, e = j & 15;
        int wc = w0 - 1 + p;
        float4 v = make_float4(0.f, 0.f, 0.f, 0.f);
        if ((unsigned)hr < (unsigned)HH && (unsigned)wc < (unsigned)WW)
            v = *(const float4*)(in + ((size_t)((b*HH + hr)*WW + wc))*CH + e*4);
        __nv_bfloat162 h01 = __floats2bfloat162_rn(v.x, v.y);
        __nv_bfloat162 h23 = __floats2bfloat162_rn(v.z, v.w);
        float2 f01 = __bfloat1622float2(h01);
        float2 f23 = __bfloat1622float2(h23);
        __nv_bfloat162 l01 = __floats2bfloat162_rn(v.x - f01.x, v.y - f01.y);
        __nv_bfloat162 l23 = __floats2bfloat162_rn(v.z - f23.x, v.w - f23.y);
        unsigned int uh01, uh23, ul01, ul23;
        memcpy(&uh01, &h01, 4); memcpy(&uh23, &h23, 4);
        memcpy(&ul01, &l01, 4); memcpy(&ul23, &l23, 4);
        uint32_t addr = pbase + (uint32_t)p*128
                      + (uint32_t)((((e >> 1) ^ (p & 7)) << 4) + (e & 1)*8);
        sts64(sb + OG_PH + addr, uh01, uh23);
        sts64(sb + OG_PL + addr, ul01, ul23);
    }
}

__global__ __launch_bounds__(128, 2)
void k_offgemm(const float* __restrict__ in,
               const __nv_bfloat16* __restrict__ wh,
               const __nv_bfloat16* __restrict__ wl,
               const float* __restrict__ boff) {
    extern __shared__ char smem[];
    uint32_t sb = smem_u32(smem);
    int t = threadIdx.x;
    int w = t >> 5, lane = t & 31;
    int w0 = blockIdx.x * 64, h0 = blockIdx.y * OG_ROWS, b = blockIdx.z;

    // load B (hi/lo): 216 rows x 128B, per-row XOR swizzle (key = row&7; 24%8==0)
    {
        const uint4* g4h = (const uint4*)wh;
        const uint4* g4l = (const uint4*)wl;
        for (int j = t; j < 1728; j += 128) {
            int row = j >> 3, q = j & 7;
            uint32_t o = (uint32_t)row*128 + (uint32_t)((q ^ (row & 7)) << 4);
            sts128(sb + OG_BH + o, g4h[j]);
            sts128(sb + OG_BL + o, g4l[j]);
        }
    }
    // initial 3 planes: h0-1, h0, h0+1
    og_loadplane(sb, in, b, w0, h0 - 1, t);
    og_loadplane(sb, in, b, w0, h0,     t);
    og_loadplane(sb, in, b, w0, h0 + 1, t);
    __syncthreads();

    int m = lane >> 3, r = lane & 7;
    int apx = 16*w + (m & 1)*8 + r;      // pixel 0..63
    int ac0 = m >> 1;
    int bochp = (m >> 1)*8 + r, bc0 = m & 1;
    int l16 = lane & 15, r2 = l16 & 7, cH = l16 >> 3;   // x2 address lanes
    float* stg = (float*)(smem + OG_STG);
    int sg = lane >> 2, tid4 = lane & 3;

    for (int ry = 0; ry < OG_ROWS; ry++) {
        int habs = h0 + ry;
        float acc[3][4];
#pragma unroll
        for (int n = 0; n < 3; n++)
#pragma unroll
            for (int j = 0; j < 4; j++) acc[n][j] = 0.f;

#pragma unroll
        for (int tap = 0; tap < 9; tap++) {
            int kx = tap / 3, ky = tap - kx*3;
            int hr = habs - 1 + kx;
            uint32_t aoffp = (uint32_t)((hr + 3) % 3) * 8448u;
            int arow = apx + ky;
            uint32_t aoff = aoffp + (uint32_t)arow*128;
            int akey = arow & 7;
            uint32_t bRow01 = (uint32_t)(tap*24 + bochp)*128;        // och 0-15 via x4
            uint32_t bRow2  = (uint32_t)(tap*24 + 16 + r2)*128;      // och 16-23 via x2
#pragma unroll
            for (int kk = 0; kk < 4; kk++) {
                uint32_t ax  = aoff + (uint32_t)(((kk*2 + ac0) ^ akey) << 4);
                uint32_t bx  = (uint32_t)(((kk*2 + bc0) ^ r) << 4);
                uint32_t bx2 = (uint32_t)(((kk*2 + cH) ^ r2) << 4);
                uint32_t ah[4], al[4], b01h[4], b01l[4], b2h[2], b2l[2];
                ldsm4(ah, sb + OG_PH + ax);
                ldsm4(al, sb + OG_PL + ax);
                ldsm4(b01h, sb + OG_BH + bRow01 + bx);
                ldsm4(b01l, sb + OG_BL + bRow01 + bx);
                ldsm2(b2h, sb + OG_BH + bRow2 + bx2);
                ldsm2(b2l, sb + OG_BL + bRow2 + bx2);
                mma16816(acc[0], ah, b01h[0], b01h[1]);
                mma16816(acc[1], ah, b01h[2], b01h[3]);
                mma16816(acc[2], ah, b2h[0],  b2h[1]);
                mma16816(acc[0], ah, b01l[0], b01l[1]);
                mma16816(acc[1], ah, b01l[2], b01l[3]);
                mma16816(acc[2], ah, b2l[0],  b2l[1]);
                mma16816(acc[0], al, b01h[0], b01h[1]);
                mma16816(acc[1], al, b01h[2], b01h[3]);
                mma16816(acc[2], al, b2h[0],  b2h[1]);
            }
        }

        // epilogue: bias + stage 64x24 fp32 in dedicated stg
#pragma unroll
        for (int nt = 0; nt < 3; nt++) {
            int col = nt*8 + tid4*2;
            float b0v = (col     < NOFF) ? boff[col]     : 0.f;
            float b1v = (col + 1 < NOFF) ? boff[col + 1] : 0.f;
            int row0 = 16*w + sg;
            stg[row0*24 + col]       = acc[nt][0] + b0v;
            stg[row0*24 + col + 1]   = acc[nt][1] + b1v;
            stg[(row0+8)*24 + col]   = acc[nt][2] + b0v;
            stg[(row0+8)*24 + col+1] = acc[nt][3] + b1v;
        }
        __syncthreads();   // all mma reads + stg writes complete

        // write g_off; overlap next plane load (recycled slot is safe post-sync)
        int px = t >> 1, half = t & 1;
        int wpos = w0 + px;
        if (wpos < WW) {
            int base = ((b*HH + habs)*WW + wpos)*NOFF + half*9;
#pragma unroll
            for (int i = 0; i < 9; i++)
                g_off[base + i] = stg[px*24 + half*9 + i];
        }
        if (ry < OG_ROWS - 1)
            og_loadplane(sb, in, b, w0, habs + 2, t);
        __syncthreads();   // plane stores + stg reads done before next row
    }
}

// ---------------- gather: bilinear sample -> bf16 hi/lo ----------------
__global__ __launch_bounds__(256) void k_gather(const float* __restrict__ in,
                                                __nv_bfloat16* __restrict__ xgh,
                                                __nv_bfloat16* __restrict__ xgl) {
    __shared__ int4   gA[288];
    __shared__ float4 gW[288];
    __shared__ int    gO[288];
    int t = threadIdx.x;
    int pix0 = blockIdx.x * 32;
    int b = pix0 / HW; int hw = pix0 - b*HW;
    int h = hw / WW;  int w0 = hw - h*WW;

    for (int j = t; j < 288; j += 256) {
        int p = j / 9; int i = j - p*9;
        int pix = pix0 + p;
        float ox = g_off[pix*NOFF + i];
        float oy = g_off[pix*NOFF + 9 + i];
        float px = (float)(h + (i/3)) + ox;
        float py = (float)(w0 + p + (i%3)) + oy;
        float fx = floorf(px), fy = floorf(py);
        int x0 = (int)fx, y0 = (int)fy;
        int x1 = x0 + 1, y1 = y0 + 1;
        x0 = min(max(x0, 0), HH-1); x1 = min(max(x1, 0), HH-1);
        y0 = min(max(y0, 0), WW-1); y1 = min(max(y1, 0), WW-1);
        float pxc = fminf(fmaxf(px, 0.f), (float)(HH-1));
        float pyc = fminf(fmaxf(py, 0.f), (float)(WW-1));
        float wx0 = 1.f + (float)x0 - pxc;
        float wx1 = 1.f - (float)x1 + pxc;
        float wy0 = 1.f + (float)y0 - pyc;
        float wy1 = 1.f - (float)y1 + pyc;
        int base = b * HW;
        gA[j] = make_int4((base + x0*WW + y0)*CH, (base + x1*WW + y1)*CH,
                          (base + x0*WW + y1)*CH, (base + x1*WW + y0)*CH);
        gW[j] = make_float4(wx0*wy0, wx1*wy1, wx0*wy1, wx1*wy0);
        gO[j] = pix*KK + i*64;
    }
    __syncthreads();

    int c4 = (t & 15) * 4;
    int d0 = t >> 4;
#pragma unroll 3
    for (int it = 0; it < 18; it++) {
        int desc = d0 + it*16;
        int4 a = gA[desc]; float4 g = gW[desc];
        float4 v0 = *(const float4*)(in + a.x + c4);
        float4 v1 = *(const float4*)(in + a.y + c4);
        float4 v2 = *(const float4*)(in + a.z + c4);
        float4 v3 = *(const float4*)(in + a.w + c4);
        float4 r;
        r.x = fmaf(g.w, v3.x, fmaf(g.z, v2.x, fmaf(g.y, v1.x, g.x*v0.x)));
        r.y = fmaf(g.w, v3.y, fmaf(g.z, v2.y, fmaf(g.y, v1.y, g.x*v0.y)));
        r.z = fmaf(g.w, v3.z, fmaf(g.z, v2.z, fmaf(g.y, v1.z, g.x*v0.z)));
        r.w = fmaf(g.w, v3.w, fmaf(g.z, v2.w, fmaf(g.y, v1.w, g.x*v0.w)));
        __nv_bfloat162 h01 = __floats2bfloat162_rn(r.x, r.y);
        __nv_bfloat162 h23 = __floats2bfloat162_rn(r.z, r.w);
        float2 f01 = __bfloat1622float2(h01);
        float2 f23 = __bfloat1622float2(h23);
        __nv_bfloat162 l01 = __floats2bfloat162_rn(r.x - f01.x, r.y - f01.y);
        __nv_bfloat162 l23 = __floats2bfloat162_rn(r.z - f23.x, r.w - f23.y);
        unsigned int uh01, uh23, ul01, ul23;
        memcpy(&uh01, &h01, 4); memcpy(&uh23, &h23, 4);
        memcpy(&ul01, &l01, 4); memcpy(&ul23, &l23, 4);
        size_t off = (size_t)gO[desc] + c4;
        *(uint2*)(xgh + off) = make_uint2(uh01, uh23);
        *(uint2*)(xgl + off) = make_uint2(ul01, ul23);
    }
}

// ---------------- mma.sync bf16 GEMM: 128px x 64och, K=576, hi/lo split ----------------
#define SM_AH   0
#define SM_AL   16384
#define SM_BH   32768
#define SM_BL   40960
#define SM_TOTAL 49152

__global__ __launch_bounds__(256, 2)
void k_gemmtc(const __nv_bfloat16* __restrict__ xh,
              const __nv_bfloat16* __restrict__ xl,
              const __nv_bfloat16* __restrict__ wh,
              const __nv_bfloat16* __restrict__ wl,
              float* __restrict__ yout) {
    extern __shared__ char smem[];
    uint32_t sb = smem_u32(smem);
    int t = threadIdx.x;
    int w = t >> 5, lane = t & 31;
    int pix0 = blockIdx.x * 128;

    int apx = t >> 1, ahalf = t & 1;
    int boch = t >> 2, bq = t & 3;
    const uint4* gah = (const uint4*)(xh + (size_t)(pix0 + apx)*KK) + ahalf*4;
    const uint4* gal = (const uint4*)(xl + (size_t)(pix0 + apx)*KK) + ahalf*4;
    const uint4* gbh = (const uint4*)wh + boch*8 + bq*2;
    const uint4* gbl = (const uint4*)wl + boch*8 + bq*2;
    int asw = apx & 7, bsw = boch & 7;

    int pg = w >> 1, og = w & 1;
    int m = lane >> 3, r = lane & 7;
    uint32_t aOff0 = (uint32_t)(32*pg + (m & 1)*8 + r) * 128;
    uint32_t aOff1 = aOff0 + 16*128;
    int ac0 = m >> 1;
    int bochp = (m >> 1)*8 + r;
    int bc0 = m & 1;
    int obase = 32*og;

    float acc[2][4][4];
#pragma unroll
    for (int rt = 0; rt < 2; rt++)
#pragma unroll
        for (int n = 0; n < 4; n++)
#pragma unroll
            for (int j = 0; j < 4; j++) acc[rt][n][j] = 0.f;

    uint4 ra[4], rl[4], rbh[2], rbl[2];
#define LOADCH(kc) do { \
        ra[0]=gah[(kc)*8+0]; ra[1]=gah[(kc)*8+1]; ra[2]=gah[(kc)*8+2]; ra[3]=gah[(kc)*8+3]; \
        rl[0]=gal[(kc)*8+0]; rl[1]=gal[(kc)*8+1]; rl[2]=gal[(kc)*8+2]; rl[3]=gal[(kc)*8+3]; \
        rbh[0]=gbh[(kc)*512+0]; rbh[1]=gbh[(kc)*512+1]; \
        rbl[0]=gbl[(kc)*512+0]; rbl[1]=gbl[(kc)*512+1]; \
    } while (0)

    LOADCH(0);
    for (int kc = 0; kc < 9; kc++) {
        __syncthreads();
#pragma unroll
        for (int q = 0; q < 4; q++) {
            uint32_t o = (uint32_t)apx*128 + (uint32_t)(((ahalf*4 + q) ^ asw) << 4);
            sts128(sb + SM_AH + o, ra[q]);
            sts128(sb + SM_AL + o, rl[q]);
        }
#pragma unroll
        for (int q = 0; q < 2; q++) {
            uint32_t o = (uint32_t)boch*128 + (uint32_t)(((bq*2 + q) ^ bsw) << 4);
            sts128(sb + SM_BH + o, rbh[q]);
            sts128(sb + SM_BL + o, rbl[q]);
        }
        __syncthreads();
        if (kc < 8) LOADCH(kc + 1);

#pragma unroll
        for (int kk = 0; kk < 4; kk++) {
            uint32_t ah0[4], al0[4], ah1[4], al1[4];
            uint32_t kx = (uint32_t)(((kk*2 + ac0) ^ r) << 4);
            ldsm4(ah0, sb + SM_AH + aOff0 + kx);
            ldsm4(al0, sb + SM_AL + aOff0 + kx);
            ldsm4(ah1, sb + SM_AH + aOff1 + kx);
            ldsm4(al1, sb + SM_AL + aOff1 + kx);
            uint32_t bco = (uint32_t)(((kk*2 + bc0) ^ r) << 4);
#pragma unroll
            for (int nt = 0; nt < 2; nt++) {
                uint32_t bh[4], bl[4];
                uint32_t bo = (uint32_t)(obase + 16*nt + bochp)*128 + bco;
                ldsm4(bh, sb + SM_BH + bo);
                ldsm4(bl, sb + SM_BL + bo);
                mma16816(acc[0][2*nt],   ah0, bh[0], bh[1]);
                mma16816(acc[0][2*nt+1], ah0, bh[2], bh[3]);
                mma16816(acc[0][2*nt],   ah0, bl[0], bl[1]);
                mma16816(acc[0][2*nt+1], ah0, bl[2], bl[3]);
                mma16816(acc[0][2*nt],   al0, bh[0], bh[1]);
                mma16816(acc[0][2*nt+1], al0, bh[2], bh[3]);
                mma16816(acc[1][2*nt],   ah1, bh[0], bh[1]);
                mma16816(acc[1][2*nt+1], ah1, bh[2], bh[3]);
                mma16816(acc[1][2*nt],   ah1, bl[0], bl[1]);
                mma16816(acc[1][2*nt+1], ah1, bl[2], bl[3]);
                mma16816(acc[1][2*nt],   al1, bh[0], bh[1]);
                mma16816(acc[1][2*nt+1], al1, bh[2], bh[3]);
            }
        }
    }
#undef LOADCH

    __syncthreads();
    float* stg = (float*)smem;
    int g = lane >> 2, tid4 = lane & 3;
#pragma unroll
    for (int rt = 0; rt < 2; rt++) {
#pragma unroll
        for (int n = 0; n < 4; n++) {
            int row0 = 32*pg + 16*rt + g;
            int col = obase + n*8 + tid4*2;
            *(float2*)(stg + row0*64 + col)     = make_float2(acc[rt][n][0], acc[rt][n][1]);
            *(float2*)(stg + (row0+8)*64 + col) = make_float2(acc[rt][n][2], acc[rt][n][3]);
        }
    }
    __syncthreads();

    int och = t & 63, grp = t >> 6;
    float s = 0.f, q = 0.f;
#pragma unroll 4
    for (int j = 0; j < 32; j++) {
        float v = stg[(grp*32 + j)*64 + och];
        s += v;
        q = fmaf(v, v, q);
    }
    float* rs = (float*)(smem + SM_BH);
    float* rq = rs + 256;
    rs[t] = s; rq[t] = q;

    float4* stg4 = (float4*)stg;
    float4* y4 = (float4*)(yout + (size_t)pix0*CH);
#pragma unroll
    for (int j = 0; j < 8; j++) y4[j*256 + t] = stg4[j*256 + t];

    __syncthreads();
    if (t < 64) {
        s = rs[t] + rs[t+64] + rs[t+128] + rs[t+192];
        q = rq[t] + rq[t+64] + rq[t+128] + rq[t+192];
        g_sp[blockIdx.x*64 + t] = s;
        g_qp[blockIdx.x*64 + t] = q;
    }
}

// ---------------- BN finish: reduce 784 partials ----------------
__global__ __launch_bounds__(256) void k_bnfinish(const float* __restrict__ gamma,
                                                  const float* __restrict__ beta) {
    __shared__ float ss[256], sq[256];
    int t = threadIdx.x;
    int c = t & 63, sub = t >> 6;
    float s = 0.f, q = 0.f;
    for (int i = sub; i < GEMMBLKS; i += 4) {
        s += g_sp[i*64 + c];
        q += g_qp[i*64 + c];
    }
    ss[t] = s; sq[t] = q;
    __syncthreads();
    if (t < 64) {
        s = ss[t] + ss[t+64] + ss[t+128] + ss[t+192];
        q = sq[t] + sq[t+64] + sq[t+128] + sq[t+192];
        float inv = 1.f / (float)NPIX;
        float mean = s * inv;
        float var = fmaxf(q * inv - mean*mean, 0.f);
        float r = rsqrtf(var + 1e-5f);
        float a = gamma[t] * r;
        g_ab[t] = a;
        g_ab[64 + t] = beta[t] - mean * a;
    }
}

// ---------------- BN apply + relu, NHWC -> NHWC (stage-1 output) ----------------
__global__ __launch_bounds__(256) void k_bnapply_nhwc(const float* __restrict__ y) {
    int v = blockIdx.x * 256 + threadIdx.x;
    float4 t4 = ((const float4*)y)[v];
    int c = (v & 15) * 4;
    float4 r;
    r.x = fmaxf(fmaf(t4.x, g_ab[c+0], g_ab[64+c+0]), 0.f);
    r.y = fmaxf(fmaf(t4.y, g_ab[c+1], g_ab[64+c+1]), 0.f);
    r.z = fmaxf(fmaf(t4.z, g_ab[c+2], g_ab[64+c+2]), 0.f);
    r.w = fmaxf(fmaf(t4.w, g_ab[c+3], g_ab[64+c+3]), 0.f);
    ((float4*)g_y1n)[v] = r;
}

// ---------------- BN apply + relu + NHWC -> NCHW (final output) ----------------
__global__ __launch_bounds__(256) void k_bnapply_nchw(const float* __restrict__ y,
                                                      float* __restrict__ out) {
    __shared__ float tile[64*33];
    int t = threadIdx.x;
    int pix0 = blockIdx.x * 32;
    int b = pix0 / HW, hw0 = pix0 - b*HW;
    int c = t & 63, q = t >> 6;
    float a = g_ab[c], bb = g_ab[64 + c];
#pragma unroll
    for (int j = 0; j < 8; j++) {
        int p = q*8 + j;
        float v = y[(pix0 + p)*CH + c];
        tile[c*33 + p] = fmaxf(fmaf(v, a, bb), 0.f);
    }
    __syncthreads();
    int p2 = t & 31, cq = t >> 5;
#pragma unroll
    for (int j = 0; j < 8; j++) {
        int cc = cq*8 + j;
        out[(b*CH + cc)*HW + hw0 + p2] = tile[cc*33 + p2];
    }
}

// ---------------- launch ----------------
extern "C" void kernel_launch(void* const* d_in, const int* in_sizes, int n_in,
                              void* d_out, int out_size) {
    const float* x      = (const float*)d_in[0];
    const float* woff1  = (const float*)d_in[1];
    const float* boff1  = (const float*)d_in[2];
    const float* wconv1 = (const float*)d_in[3];
    const float* gamma1 = (const float*)d_in[4];
    const float* beta1  = (const float*)d_in[5];
    const float* woff2  = (const float*)d_in[6];
    const float* boff2  = (const float*)d_in[7];
    const float* wconv2 = (const float*)d_in[8];
    const float* gamma2 = (const float*)d_in[9];
    const float* beta2  = (const float*)d_in[10];
    float* out = (float*)d_out;

    float *p_xh, *p_y1n, *p_yraw;
    __nv_bfloat16 *p_xgh, *p_xgl, *p_wh1, *p_wl1, *p_wh2, *p_wl2;
    __nv_bfloat16 *p_woh1, *p_wol1, *p_woh2, *p_wol2;
    cudaGetSymbolAddress((void**)&p_xh,   g_xh);
    cudaGetSymbolAddress((void**)&p_y1n,  g_y1n);
    cudaGetSymbolAddress((void**)&p_yraw, g_yraw);
    cudaGetSymbolAddress((void**)&p_xgh,  g_xgh);
    cudaGetSymbolAddress((void**)&p_xgl,  g_xgl);
    cudaGetSymbolAddress((void**)&p_wh1,  g_wh1);
    cudaGetSymbolAddress((void**)&p_wl1,  g_wl1);
    cudaGetSymbolAddress((void**)&p_wh2,  g_wh2);
    cudaGetSymbolAddress((void**)&p_wl2,  g_wl2);
    cudaGetSymbolAddress((void**)&p_woh1, g_woh1);
    cudaGetSymbolAddress((void**)&p_wol1, g_wol1);
    cudaGetSymbolAddress((void**)&p_woh2, g_woh2);
    cudaGetSymbolAddress((void**)&p_wol2, g_wol2);

    cudaFuncSetAttribute(k_offgemm, cudaFuncAttributeMaxDynamicSharedMemorySize, OG_SMEM);
    cudaFuncSetAttribute(k_gemmtc,  cudaFuncAttributeMaxDynamicSharedMemorySize, SM_TOTAL);

    // stage 1  (k_offgemm is launch 4 -> ncu capture slot)
    k_nchw2nhwc<<<dim3(HW/32, 2, BATCH), dim3(32, 8)>>>(x);                                // 1
    k_prepall<<<198, 256>>>(wconv1, woff1, p_wh1, p_wl1, p_woh1, p_wol1);                  // 2
    k_prepall<<<198, 256>>>(wconv2, woff2, p_wh2, p_wl2, p_woh2, p_wol2);                  // 3
    k_offgemm<<<dim3(4, HH/OG_ROWS, BATCH), 128, OG_SMEM>>>(p_xh, p_woh1, p_wol1, boff1);  // 4
    k_gather<<<NPIX/32, 256>>>(p_xh, p_xgh, p_xgl);                                        // 5
    k_gemmtc<<<GEMMBLKS, 256, SM_TOTAL>>>(p_xgh, p_xgl, p_wh1, p_wl1, p_yraw);             // 6
    k_bnfinish<<<1, 256>>>(gamma1, beta1);                                                 // 7
    k_bnapply_nhwc<<<NPIX*CH/4/256, 256>>>(p_yraw);                                        // 8

    // stage 2
    k_offgemm<<<dim3(4, HH/OG_ROWS, BATCH), 128, OG_SMEM>>>(p_y1n, p_woh2, p_wol2, boff2); // 9
    k_gather<<<NPIX/32, 256>>>(p_y1n, p_xgh, p_xgl);                                       // 10
    k_gemmtc<<<GEMMBLKS, 256, SM_TOTAL>>>(p_xgh, p_xgl, p_wh2, p_wl2, p_yraw);             // 11
    k_bnfinish<<<1, 256>>>(gamma2, beta2);                                                 // 12
    k_bnapply_nchw<<<NPIX/32, 256>>>(p_yraw, out);                                         // 13
}